// round 2
// baseline (speedup 1.0000x reference)
#include <cuda_runtime.h>

#define Nn 50000
#define Ee 1600000
#define CC 128
#define HH 8

// ---- scratch (static __device__: allocation-free) ----
__device__ float g_emb[Nn * CC];     // 25.6 MB
__device__ float g_left[Nn * HH];
__device__ float g_right[Nn * HH];
__device__ int   g_deg[Nn];
__device__ int   g_off[Nn + 1];
__device__ int   g_cur[Nn];
__device__ int   g_csr[Ee];          // 6.4 MB

// ------------------------------------------------------------------
// K0: zero the degree histogram
// ------------------------------------------------------------------
__global__ void k_zero(int n) {
    int i = blockIdx.x * blockDim.x + threadIdx.x;
    if (i < n) g_deg[i] = 0;
}

// ------------------------------------------------------------------
// K1: emb = X @ W^T  + fused per-node logits left/right
// block: 256 threads, 32 nodes per block, K chunked by 32.
// Warp ty owns nodes m0+ty+8j (j=0..3); lane owns channels 4*lane..4*lane+3.
// ------------------------------------------------------------------
__global__ void k_gemm(const float* __restrict__ X, const float* __restrict__ W,
                       const float* __restrict__ aL, const float* __restrict__ aR, int n) {
    __shared__ float Wsh[32][132];   // Wsh[k][o] = W[o][kc+k]
    __shared__ float Xsh[32][33];    // Xsh[m][k]

    const int tid  = threadIdx.x;
    const int lane = tid & 31;
    const int ty   = tid >> 5;       // warp id 0..7
    const int c0   = lane * 4;       // 4 consecutive output channels per lane
    const int m0   = blockIdx.x * 32;

    float4 acc[4];
    #pragma unroll
    for (int j = 0; j < 4; j++) acc[j] = make_float4(0.f, 0.f, 0.f, 0.f);

    for (int kc = 0; kc < CC; kc += 32) {
        const int kk = lane;
        #pragma unroll
        for (int ii = 0; ii < 16; ii++) {
            int o = ty + 8 * ii;
            Wsh[kk][o] = W[o * CC + kc + kk];
        }
        #pragma unroll
        for (int ii = 0; ii < 4; ii++) {
            int m = ty + 8 * ii;
            int node = m0 + m;
            Xsh[m][kk] = (node < n) ? X[node * CC + kc + kk] : 0.f;
        }
        __syncthreads();

        #pragma unroll
        for (int k = 0; k < 32; k++) {
            const float4 wv = *(const float4*)&Wsh[k][c0];
            #pragma unroll
            for (int j = 0; j < 4; j++) {
                float xv = Xsh[ty + 8 * j][k];
                acc[j].x += xv * wv.x;
                acc[j].y += xv * wv.y;
                acc[j].z += xv * wv.z;
                acc[j].w += xv * wv.w;
            }
        }
        __syncthreads();
    }

    // epilogue: store emb + fused left/right logits
    const int h     = lane >> 2;          // head of this lane's channels
    const int cbase = (lane & 3) * 4;     // channel-within-head base
    const float al0 = aL[(cbase + 0) * HH + h], al1 = aL[(cbase + 1) * HH + h];
    const float al2 = aL[(cbase + 2) * HH + h], al3 = aL[(cbase + 3) * HH + h];
    const float ar0 = aR[(cbase + 0) * HH + h], ar1 = aR[(cbase + 1) * HH + h];
    const float ar2 = aR[(cbase + 2) * HH + h], ar3 = aR[(cbase + 3) * HH + h];

    #pragma unroll
    for (int j = 0; j < 4; j++) {
        int node = m0 + ty + 8 * j;
        float4 a = acc[j];
        float l = a.x * al0 + a.y * al1 + a.z * al2 + a.w * al3;
        float r = a.x * ar0 + a.y * ar1 + a.z * ar2 + a.w * ar3;
        l += __shfl_xor_sync(0xffffffffu, l, 1);
        l += __shfl_xor_sync(0xffffffffu, l, 2);
        r += __shfl_xor_sync(0xffffffffu, r, 1);
        r += __shfl_xor_sync(0xffffffffu, r, 2);
        if (node < n) {
            *(float4*)&g_emb[node * CC + c0] = a;
            if ((lane & 3) == 0) {
                g_left [node * HH + h] = l;
                g_right[node * HH + h] = r;
            }
        }
    }
}

// ------------------------------------------------------------------
// K2: degree histogram over dst   (edge_index is int32: [src(E) | dst(E)])
// ------------------------------------------------------------------
__global__ void k_hist(const int* __restrict__ ei, int e) {
    int i = blockIdx.x * blockDim.x + threadIdx.x;
    if (i < e) atomicAdd(&g_deg[ei[e + i]], 1);
}

// ------------------------------------------------------------------
// K3: exclusive scan of degrees -> offsets (+ cursor copy). Single block.
// ------------------------------------------------------------------
__global__ void k_scan(int n) {
    __shared__ int wsums[32];
    __shared__ int carry_sh;
    int tid = threadIdx.x;
    if (tid == 0) carry_sh = 0;
    __syncthreads();

    for (int base = 0; base < n; base += 1024) {
        int i = base + tid;
        int v = (i < n) ? g_deg[i] : 0;
        int x = v;
        #pragma unroll
        for (int d = 1; d < 32; d <<= 1) {
            int y = __shfl_up_sync(0xffffffffu, x, d);
            if ((tid & 31) >= d) x += y;
        }
        if ((tid & 31) == 31) wsums[tid >> 5] = x;
        __syncthreads();
        if (tid < 32) {
            int s = wsums[tid];
            #pragma unroll
            for (int d = 1; d < 32; d <<= 1) {
                int y = __shfl_up_sync(0xffffffffu, s, d);
                if (tid >= d) s += y;
            }
            wsums[tid] = s;
        }
        __syncthreads();
        int wp   = (tid >= 32) ? wsums[(tid >> 5) - 1] : 0;
        int incl = x + wp;
        int carry = carry_sh;
        if (i < n) {
            int excl = carry + incl - v;
            g_off[i] = excl;
            g_cur[i] = excl;
        }
        int total = carry + wsums[31];
        __syncthreads();
        if (tid == 0) carry_sh = total;
        __syncthreads();
    }
    if (tid == 0) g_off[n] = carry_sh;
}

// ------------------------------------------------------------------
// K4: scatter edges into CSR (by dst), storing src
// ------------------------------------------------------------------
__global__ void k_scatter(const int* __restrict__ ei, int e) {
    int i = blockIdx.x * blockDim.x + threadIdx.x;
    if (i < e) {
        int dst = ei[e + i];
        int pos = atomicAdd(&g_cur[dst], 1);
        g_csr[pos] = ei[i];
    }
}

// ------------------------------------------------------------------
// K5: aggregation. One warp per dst node; lane owns 4 channels (head=l/4).
// out[v] = (sum_e w_e * emb[src_e]) / (sum_e w_e) + bias
// ------------------------------------------------------------------
__global__ void k_agg(const float* __restrict__ bias, float* __restrict__ out, int n) {
    int warp = (blockIdx.x * blockDim.x + threadIdx.x) >> 5;
    int lane = threadIdx.x & 31;
    if (warp >= n) return;

    int h = lane >> 2;
    float rv = g_right[warp * HH + h];
    int s0 = g_off[warp], s1 = g_off[warp + 1];

    float4 acc = make_float4(0.f, 0.f, 0.f, 0.f);
    float sumw = 0.f;

    for (int base = s0; base < s1; base += 32) {
        int idx = base + lane;
        int sv  = (idx < s1) ? g_csr[idx] : 0;
        int cnt = min(32, s1 - base);
        for (int j = 0; j < cnt; j++) {
            int s = __shfl_sync(0xffffffffu, sv, j);
            float e = g_left[s * HH + h] + rv;
            e = (e >= 0.f) ? e : 0.2f * e;
            float w = __expf(e);
            const float4 em = *(const float4*)&g_emb[s * CC + lane * 4];
            sumw  += w;
            acc.x += w * em.x;
            acc.y += w * em.y;
            acc.z += w * em.z;
            acc.w += w * em.w;
        }
    }

    float inv = (sumw > 0.f) ? (1.f / sumw) : 0.f;
    int c = lane * 4;
    float4 o;
    o.x = acc.x * inv + bias[c + 0];
    o.y = acc.y * inv + bias[c + 1];
    o.z = acc.z * inv + bias[c + 2];
    o.w = acc.w * inv + bias[c + 3];
    *(float4*)&out[warp * CC + c] = o;
}

// ------------------------------------------------------------------
extern "C" void kernel_launch(void* const* d_in, const int* in_sizes, int n_in,
                              void* d_out, int out_size) {
    const float* X    = (const float*)d_in[0];
    const int*   EI   = (const int*)d_in[1];
    const float* W    = (const float*)d_in[2];
    const float* aL   = (const float*)d_in[3];
    const float* aR   = (const float*)d_in[4];
    const float* bias = (const float*)d_in[5];
    float*       out  = (float*)d_out;

    const int n = in_sizes[0] / CC;   // 50000
    const int e = in_sizes[1] / 2;    // 1600000

    k_zero   <<<(n + 255) / 256, 256>>>(n);
    k_gemm   <<<(n + 31) / 32, 256>>>(X, W, aL, aR, n);
    k_hist   <<<(e + 255) / 256, 256>>>(EI, e);
    k_scan   <<<1, 1024>>>(n);
    k_scatter<<<(e + 255) / 256, 256>>>(EI, e);
    k_agg    <<<(n * 32 + 255) / 256, 256>>>(bias, out, n);
}

// round 4
// speedup vs baseline: 1.1856x; 1.1856x over previous
#include <cuda_runtime.h>

#define Nn 50000
#define Ee 1600000
#define CC 128
#define HH 8
#define SCAN_B 1024
#define NBLK ((Nn + SCAN_B - 1) / SCAN_B)   // 49

// ---- scratch (static __device__: allocation-free) ----
__device__ float g_emb[Nn * CC];     // 25.6 MB
__device__ float g_left[Nn * HH];
__device__ float g_right[Nn * HH];
__device__ int   g_deg[Nn];
__device__ int   g_off[Nn + 1];
__device__ int   g_cur[Nn];
__device__ int   g_csr[Ee];          // 6.4 MB
__device__ int   g_bsum[NBLK];
__device__ int   g_bsumx[NBLK];

// ------------------------------------------------------------------
// K0: zero the degree histogram
// ------------------------------------------------------------------
__global__ void k_zero(int n) {
    int i = blockIdx.x * blockDim.x + threadIdx.x;
    if (i < n) g_deg[i] = 0;
}

// ------------------------------------------------------------------
// K1: emb = X @ W^T  + fused per-node logits left/right
// ------------------------------------------------------------------
__global__ void k_gemm(const float* __restrict__ X, const float* __restrict__ W,
                       const float* __restrict__ aL, const float* __restrict__ aR, int n) {
    __shared__ float Wsh[32][132];   // Wsh[k][o] = W[o][kc+k]
    __shared__ float Xsh[32][33];    // Xsh[m][k]

    const int tid  = threadIdx.x;
    const int lane = tid & 31;
    const int ty   = tid >> 5;       // warp id 0..7
    const int c0   = lane * 4;
    const int m0   = blockIdx.x * 32;

    float4 acc[4];
    #pragma unroll
    for (int j = 0; j < 4; j++) acc[j] = make_float4(0.f, 0.f, 0.f, 0.f);

    for (int kc = 0; kc < CC; kc += 32) {
        const int kk = lane;
        #pragma unroll
        for (int ii = 0; ii < 16; ii++) {
            int o = ty + 8 * ii;
            Wsh[kk][o] = W[o * CC + kc + kk];
        }
        #pragma unroll
        for (int ii = 0; ii < 4; ii++) {
            int m = ty + 8 * ii;
            int node = m0 + m;
            Xsh[m][kk] = (node < n) ? X[node * CC + kc + kk] : 0.f;
        }
        __syncthreads();

        #pragma unroll
        for (int k = 0; k < 32; k++) {
            const float4 wv = *(const float4*)&Wsh[k][c0];
            #pragma unroll
            for (int j = 0; j < 4; j++) {
                float xv = Xsh[ty + 8 * j][k];
                acc[j].x += xv * wv.x;
                acc[j].y += xv * wv.y;
                acc[j].z += xv * wv.z;
                acc[j].w += xv * wv.w;
            }
        }
        __syncthreads();
    }

    const int h     = lane >> 2;
    const int cbase = (lane & 3) * 4;
    const float al0 = aL[(cbase + 0) * HH + h], al1 = aL[(cbase + 1) * HH + h];
    const float al2 = aL[(cbase + 2) * HH + h], al3 = aL[(cbase + 3) * HH + h];
    const float ar0 = aR[(cbase + 0) * HH + h], ar1 = aR[(cbase + 1) * HH + h];
    const float ar2 = aR[(cbase + 2) * HH + h], ar3 = aR[(cbase + 3) * HH + h];

    #pragma unroll
    for (int j = 0; j < 4; j++) {
        int node = m0 + ty + 8 * j;
        float4 a = acc[j];
        float l = a.x * al0 + a.y * al1 + a.z * al2 + a.w * al3;
        float r = a.x * ar0 + a.y * ar1 + a.z * ar2 + a.w * ar3;
        l += __shfl_xor_sync(0xffffffffu, l, 1);
        l += __shfl_xor_sync(0xffffffffu, l, 2);
        r += __shfl_xor_sync(0xffffffffu, r, 1);
        r += __shfl_xor_sync(0xffffffffu, r, 2);
        if (node < n) {
            *(float4*)&g_emb[node * CC + c0] = a;
            if ((lane & 3) == 0) {
                g_left [node * HH + h] = l;
                g_right[node * HH + h] = r;
            }
        }
    }
}

// ------------------------------------------------------------------
// K2: degree histogram over dst   (edge_index int32: [src(E) | dst(E)])
// ------------------------------------------------------------------
__global__ void k_hist(const int* __restrict__ ei, int e) {
    int i = blockIdx.x * blockDim.x + threadIdx.x;
    if (i < e) atomicAdd(&g_deg[ei[e + i]], 1);
}

// ------------------------------------------------------------------
// K3a: per-block exclusive scan (1024 elems/block) + block totals
// ------------------------------------------------------------------
__device__ __forceinline__ int block_scan_incl(int v, int tid, int* wsums) {
    int x = v;
    #pragma unroll
    for (int d = 1; d < 32; d <<= 1) {
        int y = __shfl_up_sync(0xffffffffu, x, d);
        if ((tid & 31) >= d) x += y;
    }
    if ((tid & 31) == 31) wsums[tid >> 5] = x;
    __syncthreads();
    if (tid < 32) {
        int s = wsums[tid];
        #pragma unroll
        for (int d = 1; d < 32; d <<= 1) {
            int y = __shfl_up_sync(0xffffffffu, s, d);
            if (tid >= d) s += y;
        }
        wsums[tid] = s;
    }
    __syncthreads();
    int wp = (tid >= 32) ? wsums[(tid >> 5) - 1] : 0;
    return x + wp;   // inclusive
}

__global__ void k_scanA(int n) {
    __shared__ int wsums[32];
    int tid = threadIdx.x;
    int i = blockIdx.x * SCAN_B + tid;
    int v = (i < n) ? g_deg[i] : 0;
    int incl = block_scan_incl(v, tid, wsums);
    if (i < n) g_off[i] = incl - v;            // local exclusive
    if (tid == SCAN_B - 1) g_bsum[blockIdx.x] = incl;
}

// K3b: scan the block totals (single tiny block)
__global__ void k_scanB(int n) {
    __shared__ int wsums[32];
    int tid = threadIdx.x;
    int v = (tid < NBLK) ? g_bsum[tid] : 0;
    int incl = block_scan_incl(v, tid, wsums);
    if (tid < NBLK) g_bsumx[tid] = incl - v;   // exclusive block offset
    if (tid == NBLK - 1) g_off[n] = incl;      // grand total
}

// K3c: add block offsets, fill cursors
__global__ void k_scanC(int n) {
    int i = blockIdx.x * SCAN_B + threadIdx.x;
    if (i < n) {
        int o = g_off[i] + g_bsumx[blockIdx.x];
        g_off[i] = o;
        g_cur[i] = o;
    }
}

// ------------------------------------------------------------------
// K4: scatter edges into CSR (by dst), storing src
// ------------------------------------------------------------------
__global__ void k_scatter(const int* __restrict__ ei, int e) {
    int i = blockIdx.x * blockDim.x + threadIdx.x;
    if (i < e) {
        int dst = ei[e + i];
        int pos = atomicAdd(&g_cur[dst], 1);
        g_csr[pos] = ei[i];
    }
}

// ------------------------------------------------------------------
// K5: aggregation. One warp per dst node; lane owns 4 channels (head=l/4).
// ------------------------------------------------------------------
__global__ void k_agg(const float* __restrict__ bias, float* __restrict__ out, int n) {
    int warp = (blockIdx.x * blockDim.x + threadIdx.x) >> 5;
    int lane = threadIdx.x & 31;
    if (warp >= n) return;

    int h = lane >> 2;
    float rv = g_right[warp * HH + h];
    int s0 = g_off[warp], s1 = g_off[warp + 1];

    float4 acc = make_float4(0.f, 0.f, 0.f, 0.f);
    float sumw = 0.f;

    for (int base = s0; base < s1; base += 32) {
        int idx = base + lane;
        int sv  = (idx < s1) ? g_csr[idx] : 0;
        int cnt = min(32, s1 - base);
        for (int j = 0; j < cnt; j++) {
            int s = __shfl_sync(0xffffffffu, sv, j);
            float e = g_left[s * HH + h] + rv;
            e = (e >= 0.f) ? e : 0.2f * e;
            float w = __expf(e);
            const float4 em = *(const float4*)&g_emb[s * CC + lane * 4];
            sumw  += w;
            acc.x += w * em.x;
            acc.y += w * em.y;
            acc.z += w * em.z;
            acc.w += w * em.w;
        }
    }

    float inv = (sumw > 0.f) ? (1.f / sumw) : 0.f;
    int c = lane * 4;
    float4 o;
    o.x = acc.x * inv + bias[c + 0];
    o.y = acc.y * inv + bias[c + 1];
    o.z = acc.z * inv + bias[c + 2];
    o.w = acc.w * inv + bias[c + 3];
    *(float4*)&out[warp * CC + c] = o;
}

// ------------------------------------------------------------------
extern "C" void kernel_launch(void* const* d_in, const int* in_sizes, int n_in,
                              void* d_out, int out_size) {
    const float* X    = (const float*)d_in[0];
    const int*   EI   = (const int*)d_in[1];
    const float* W    = (const float*)d_in[2];
    const float* aL   = (const float*)d_in[3];
    const float* aR   = (const float*)d_in[4];
    const float* bias = (const float*)d_in[5];
    float*       out  = (float*)d_out;

    const int n = in_sizes[0] / CC;   // 50000
    const int e = in_sizes[1] / 2;    // 1600000

    k_zero   <<<(n + 255) / 256, 256>>>(n);
    k_gemm   <<<(n + 31) / 32, 256>>>(X, W, aL, aR, n);
    k_hist   <<<(e + 255) / 256, 256>>>(EI, e);
    k_scanA  <<<NBLK, SCAN_B>>>(n);
    k_scanB  <<<1, SCAN_B>>>(n);
    k_scanC  <<<NBLK, SCAN_B>>>(n);
    k_scatter<<<(e + 255) / 256, 256>>>(EI, e);
    k_agg    <<<(n * 32 + 255) / 256, 256>>>(bias, out, n);
}

// round 5
// speedup vs baseline: 1.1891x; 1.0029x over previous
#include <cuda_runtime.h>
#include <cuda_fp16.h>

#define Nn 50000
#define Ee 1600000
#define CC 128
#define HH 8
#define SCAN_B 1024
#define NBLK ((Nn + SCAN_B - 1) / SCAN_B)   // 49

// ---- scratch (static __device__: allocation-free) ----
__device__ __half g_embh[Nn * CC];   // 12.8 MB (fp16 message values)
__device__ float g_left[Nn * HH];
__device__ float g_right[Nn * HH];
__device__ int   g_deg[Nn];
__device__ int   g_off[Nn + 1];
__device__ int   g_cur[Nn];
__device__ int   g_csr[Ee];          // 6.4 MB
__device__ int   g_bsum[NBLK];
__device__ int   g_bsumx[NBLK];

// ------------------------------------------------------------------
// K0: zero the degree histogram
// ------------------------------------------------------------------
__global__ void k_zero(int n) {
    int i = blockIdx.x * blockDim.x + threadIdx.x;
    if (i < n) g_deg[i] = 0;
}

// ------------------------------------------------------------------
// K1: emb = X @ W^T  (fp32 compute) + fused left/right logits (fp32)
//     emb stored quantized to fp16 for the aggregation pass.
// ------------------------------------------------------------------
__global__ void k_gemm(const float* __restrict__ X, const float* __restrict__ W,
                       const float* __restrict__ aL, const float* __restrict__ aR, int n) {
    __shared__ float Wsh[32][132];   // Wsh[k][o] = W[o][kc+k]
    __shared__ float Xsh[32][33];    // Xsh[m][k]

    const int tid  = threadIdx.x;
    const int lane = tid & 31;
    const int ty   = tid >> 5;       // warp id 0..7
    const int c0   = lane * 4;
    const int m0   = blockIdx.x * 32;

    float4 acc[4];
    #pragma unroll
    for (int j = 0; j < 4; j++) acc[j] = make_float4(0.f, 0.f, 0.f, 0.f);

    for (int kc = 0; kc < CC; kc += 32) {
        const int kk = lane;
        #pragma unroll
        for (int ii = 0; ii < 16; ii++) {
            int o = ty + 8 * ii;
            Wsh[kk][o] = W[o * CC + kc + kk];
        }
        #pragma unroll
        for (int ii = 0; ii < 4; ii++) {
            int m = ty + 8 * ii;
            int node = m0 + m;
            Xsh[m][kk] = (node < n) ? X[node * CC + kc + kk] : 0.f;
        }
        __syncthreads();

        #pragma unroll
        for (int k = 0; k < 32; k++) {
            const float4 wv = *(const float4*)&Wsh[k][c0];
            #pragma unroll
            for (int j = 0; j < 4; j++) {
                float xv = Xsh[ty + 8 * j][k];
                acc[j].x += xv * wv.x;
                acc[j].y += xv * wv.y;
                acc[j].z += xv * wv.z;
                acc[j].w += xv * wv.w;
            }
        }
        __syncthreads();
    }

    const int h     = lane >> 2;
    const int cbase = (lane & 3) * 4;
    const float al0 = aL[(cbase + 0) * HH + h], al1 = aL[(cbase + 1) * HH + h];
    const float al2 = aL[(cbase + 2) * HH + h], al3 = aL[(cbase + 3) * HH + h];
    const float ar0 = aR[(cbase + 0) * HH + h], ar1 = aR[(cbase + 1) * HH + h];
    const float ar2 = aR[(cbase + 2) * HH + h], ar3 = aR[(cbase + 3) * HH + h];

    #pragma unroll
    for (int j = 0; j < 4; j++) {
        int node = m0 + ty + 8 * j;
        float4 a = acc[j];
        float l = a.x * al0 + a.y * al1 + a.z * al2 + a.w * al3;
        float r = a.x * ar0 + a.y * ar1 + a.z * ar2 + a.w * ar3;
        l += __shfl_xor_sync(0xffffffffu, l, 1);
        l += __shfl_xor_sync(0xffffffffu, l, 2);
        r += __shfl_xor_sync(0xffffffffu, r, 1);
        r += __shfl_xor_sync(0xffffffffu, r, 2);
        if (node < n) {
            __half2 h0 = __floats2half2_rn(a.x, a.y);
            __half2 h1 = __floats2half2_rn(a.z, a.w);
            uint2 packed;
            packed.x = *(unsigned int*)&h0;
            packed.y = *(unsigned int*)&h1;
            *(uint2*)&g_embh[node * CC + c0] = packed;
            if ((lane & 3) == 0) {
                g_left [node * HH + h] = l;
                g_right[node * HH + h] = r;
            }
        }
    }
}

// ------------------------------------------------------------------
// K2: degree histogram over dst   (edge_index int32: [src(E) | dst(E)])
// ------------------------------------------------------------------
__global__ void k_hist(const int* __restrict__ ei, int e) {
    int i = blockIdx.x * blockDim.x + threadIdx.x;
    if (i < e) atomicAdd(&g_deg[ei[e + i]], 1);
}

// ------------------------------------------------------------------
// K3: hierarchical exclusive scan
// ------------------------------------------------------------------
__device__ __forceinline__ int block_scan_incl(int v, int tid, int* wsums) {
    int x = v;
    #pragma unroll
    for (int d = 1; d < 32; d <<= 1) {
        int y = __shfl_up_sync(0xffffffffu, x, d);
        if ((tid & 31) >= d) x += y;
    }
    if ((tid & 31) == 31) wsums[tid >> 5] = x;
    __syncthreads();
    if (tid < 32) {
        int s = wsums[tid];
        #pragma unroll
        for (int d = 1; d < 32; d <<= 1) {
            int y = __shfl_up_sync(0xffffffffu, s, d);
            if (tid >= d) s += y;
        }
        wsums[tid] = s;
    }
    __syncthreads();
    int wp = (tid >= 32) ? wsums[(tid >> 5) - 1] : 0;
    return x + wp;   // inclusive
}

__global__ void k_scanA(int n) {
    __shared__ int wsums[32];
    int tid = threadIdx.x;
    int i = blockIdx.x * SCAN_B + tid;
    int v = (i < n) ? g_deg[i] : 0;
    int incl = block_scan_incl(v, tid, wsums);
    if (i < n) g_off[i] = incl - v;
    if (tid == SCAN_B - 1) g_bsum[blockIdx.x] = incl;
}

__global__ void k_scanB(int n) {
    __shared__ int wsums[32];
    int tid = threadIdx.x;
    int v = (tid < NBLK) ? g_bsum[tid] : 0;
    int incl = block_scan_incl(v, tid, wsums);
    if (tid < NBLK) g_bsumx[tid] = incl - v;
    if (tid == NBLK - 1) g_off[n] = incl;
}

__global__ void k_scanC(int n) {
    int i = blockIdx.x * SCAN_B + threadIdx.x;
    if (i < n) {
        int o = g_off[i] + g_bsumx[blockIdx.x];
        g_off[i] = o;
        g_cur[i] = o;
    }
}

// ------------------------------------------------------------------
// K4: scatter edges into CSR (by dst), storing src
// ------------------------------------------------------------------
__global__ void k_scatter(const int* __restrict__ ei, int e) {
    int i = blockIdx.x * blockDim.x + threadIdx.x;
    if (i < e) {
        int dst = ei[e + i];
        int pos = atomicAdd(&g_cur[dst], 1);
        g_csr[pos] = ei[i];
    }
}

// ------------------------------------------------------------------
// K5: aggregation. One warp per dst node; lane owns 4 channels (head=l/4).
// emb read as fp16, accumulated in fp32.
// ------------------------------------------------------------------
__global__ void k_agg(const float* __restrict__ bias, float* __restrict__ out, int n) {
    int warp = (blockIdx.x * blockDim.x + threadIdx.x) >> 5;
    int lane = threadIdx.x & 31;
    if (warp >= n) return;

    int h = lane >> 2;
    float rv = g_right[warp * HH + h];
    int s0 = g_off[warp], s1 = g_off[warp + 1];

    float4 acc = make_float4(0.f, 0.f, 0.f, 0.f);
    float sumw = 0.f;

    for (int base = s0; base < s1; base += 32) {
        int idx = base + lane;
        int sv  = (idx < s1) ? g_csr[idx] : 0;
        int cnt = min(32, s1 - base);
        for (int j = 0; j < cnt; j++) {
            int s = __shfl_sync(0xffffffffu, sv, j);
            float e = g_left[s * HH + h] + rv;
            e = (e >= 0.f) ? e : 0.2f * e;
            float w = __expf(e);
            uint2 raw = *(const uint2*)&g_embh[s * CC + lane * 4];
            __half2 h0 = *(__half2*)&raw.x;
            __half2 h1 = *(__half2*)&raw.y;
            float2 f0 = __half22float2(h0);
            float2 f1 = __half22float2(h1);
            sumw  += w;
            acc.x += w * f0.x;
            acc.y += w * f0.y;
            acc.z += w * f1.x;
            acc.w += w * f1.y;
        }
    }

    float inv = (sumw > 0.f) ? (1.f / sumw) : 0.f;
    int c = lane * 4;
    float4 o;
    o.x = acc.x * inv + bias[c + 0];
    o.y = acc.y * inv + bias[c + 1];
    o.z = acc.z * inv + bias[c + 2];
    o.w = acc.w * inv + bias[c + 3];
    *(float4*)&out[warp * CC + c] = o;
}

// ------------------------------------------------------------------
extern "C" void kernel_launch(void* const* d_in, const int* in_sizes, int n_in,
                              void* d_out, int out_size) {
    const float* X    = (const float*)d_in[0];
    const int*   EI   = (const int*)d_in[1];
    const float* W    = (const float*)d_in[2];
    const float* aL   = (const float*)d_in[3];
    const float* aR   = (const float*)d_in[4];
    const float* bias = (const float*)d_in[5];
    float*       out  = (float*)d_out;

    const int n = in_sizes[0] / CC;   // 50000
    const int e = in_sizes[1] / 2;    // 1600000

    k_zero   <<<(n + 255) / 256, 256>>>(n);
    k_gemm   <<<(n + 31) / 32, 256>>>(X, W, aL, aR, n);
    k_hist   <<<(e + 255) / 256, 256>>>(EI, e);
    k_scanA  <<<NBLK, SCAN_B>>>(n);
    k_scanB  <<<1, SCAN_B>>>(n);
    k_scanC  <<<NBLK, SCAN_B>>>(n);
    k_scatter<<<(e + 255) / 256, 256>>>(EI, e);
    k_agg    <<<(n * 32 + 255) / 256, 256>>>(bias, out, n);
}

// round 6
// speedup vs baseline: 1.3793x; 1.1600x over previous
#include <cuda_runtime.h>
#include <cuda_fp16.h>

#define Nn 50000
#define Ee 1600000
#define CC 128
#define HH 8
#define SCAN_B 1024
#define NBLK ((Nn + SCAN_B - 1) / SCAN_B)   // 49

// ---- scratch (static __device__: allocation-free) ----
__device__ __half g_embh[Nn * CC];   // 12.8 MB (fp16 message values)
__device__ float g_left[Nn * HH];
__device__ float g_right[Nn * HH];
__device__ int   g_deg[Nn];
__device__ int   g_off[Nn + 1];
__device__ int   g_cur[Nn];
__device__ int   g_csr[Ee];          // 6.4 MB
__device__ int   g_bsum[NBLK];
__device__ int   g_bsumx[NBLK];

// ------------------------------------------------------------------
// K0: zero the degree histogram
// ------------------------------------------------------------------
__global__ void k_zero(int n) {
    int i = blockIdx.x * blockDim.x + threadIdx.x;
    if (i < n) g_deg[i] = 0;
}

// ------------------------------------------------------------------
// K1: emb = X @ W^T (fp32) + fused left/right logits.
// 64-node tile, 8 accumulators/thread -> FMA-bound, not LDS-bound.
// ------------------------------------------------------------------
__global__ void k_gemm(const float* __restrict__ X, const float* __restrict__ W,
                       const float* __restrict__ aL, const float* __restrict__ aR, int n) {
    __shared__ float Wsh[32][132];   // Wsh[k][o] = W[o][kc+k]
    __shared__ float Xsh[64][33];    // Xsh[m][k]

    const int tid  = threadIdx.x;
    const int lane = tid & 31;
    const int ty   = tid >> 5;       // warp id 0..7
    const int c0   = lane * 4;
    const int m0   = blockIdx.x * 64;

    float4 acc[8];
    #pragma unroll
    for (int j = 0; j < 8; j++) acc[j] = make_float4(0.f, 0.f, 0.f, 0.f);

    for (int kc = 0; kc < CC; kc += 32) {
        const int kk = lane;
        #pragma unroll
        for (int ii = 0; ii < 16; ii++) {
            int o = ty + 8 * ii;
            Wsh[kk][o] = W[o * CC + kc + kk];
        }
        #pragma unroll
        for (int ii = 0; ii < 8; ii++) {
            int m = ty + 8 * ii;
            int node = m0 + m;
            Xsh[m][kk] = (node < n) ? X[node * CC + kc + kk] : 0.f;
        }
        __syncthreads();

        #pragma unroll
        for (int k = 0; k < 32; k++) {
            const float4 wv = *(const float4*)&Wsh[k][c0];
            #pragma unroll
            for (int j = 0; j < 8; j++) {
                float xv = Xsh[ty + 8 * j][k];
                acc[j].x += xv * wv.x;
                acc[j].y += xv * wv.y;
                acc[j].z += xv * wv.z;
                acc[j].w += xv * wv.w;
            }
        }
        __syncthreads();
    }

    const int h     = lane >> 2;
    const int cbase = (lane & 3) * 4;
    const float al0 = aL[(cbase + 0) * HH + h], al1 = aL[(cbase + 1) * HH + h];
    const float al2 = aL[(cbase + 2) * HH + h], al3 = aL[(cbase + 3) * HH + h];
    const float ar0 = aR[(cbase + 0) * HH + h], ar1 = aR[(cbase + 1) * HH + h];
    const float ar2 = aR[(cbase + 2) * HH + h], ar3 = aR[(cbase + 3) * HH + h];

    #pragma unroll
    for (int j = 0; j < 8; j++) {
        int node = m0 + ty + 8 * j;
        float4 a = acc[j];
        float l = a.x * al0 + a.y * al1 + a.z * al2 + a.w * al3;
        float r = a.x * ar0 + a.y * ar1 + a.z * ar2 + a.w * ar3;
        l += __shfl_xor_sync(0xffffffffu, l, 1);
        l += __shfl_xor_sync(0xffffffffu, l, 2);
        r += __shfl_xor_sync(0xffffffffu, r, 1);
        r += __shfl_xor_sync(0xffffffffu, r, 2);
        if (node < n) {
            __half2 h0 = __floats2half2_rn(a.x, a.y);
            __half2 h1 = __floats2half2_rn(a.z, a.w);
            uint2 packed;
            packed.x = *(unsigned int*)&h0;
            packed.y = *(unsigned int*)&h1;
            *(uint2*)&g_embh[node * CC + c0] = packed;
            if ((lane & 3) == 0) {
                g_left [node * HH + h] = l;
                g_right[node * HH + h] = r;
            }
        }
    }
}

// ------------------------------------------------------------------
// K2: degree histogram over dst
// ------------------------------------------------------------------
__global__ void k_hist(const int* __restrict__ ei, int e) {
    int i = blockIdx.x * blockDim.x + threadIdx.x;
    if (i < e) atomicAdd(&g_deg[ei[e + i]], 1);
}

// ------------------------------------------------------------------
// K3: hierarchical exclusive scan
// ------------------------------------------------------------------
__device__ __forceinline__ int block_scan_incl(int v, int tid, int* wsums) {
    int x = v;
    #pragma unroll
    for (int d = 1; d < 32; d <<= 1) {
        int y = __shfl_up_sync(0xffffffffu, x, d);
        if ((tid & 31) >= d) x += y;
    }
    if ((tid & 31) == 31) wsums[tid >> 5] = x;
    __syncthreads();
    if (tid < 32) {
        int s = wsums[tid];
        #pragma unroll
        for (int d = 1; d < 32; d <<= 1) {
            int y = __shfl_up_sync(0xffffffffu, s, d);
            if (tid >= d) s += y;
        }
        wsums[tid] = s;
    }
    __syncthreads();
    int wp = (tid >= 32) ? wsums[(tid >> 5) - 1] : 0;
    return x + wp;
}

__global__ void k_scanA(int n) {
    __shared__ int wsums[32];
    int tid = threadIdx.x;
    int i = blockIdx.x * SCAN_B + tid;
    int v = (i < n) ? g_deg[i] : 0;
    int incl = block_scan_incl(v, tid, wsums);
    if (i < n) g_off[i] = incl - v;
    if (tid == SCAN_B - 1) g_bsum[blockIdx.x] = incl;
}

__global__ void k_scanB(int n) {
    __shared__ int wsums[32];
    int tid = threadIdx.x;
    int v = (tid < NBLK) ? g_bsum[tid] : 0;
    int incl = block_scan_incl(v, tid, wsums);
    if (tid < NBLK) g_bsumx[tid] = incl - v;
    if (tid == NBLK - 1) g_off[n] = incl;
}

__global__ void k_scanC(int n) {
    int i = blockIdx.x * SCAN_B + threadIdx.x;
    if (i < n) {
        int o = g_off[i] + g_bsumx[blockIdx.x];
        g_off[i] = o;
        g_cur[i] = o;
    }
}

// ------------------------------------------------------------------
// K4: scatter edges into CSR (by dst), storing src
// ------------------------------------------------------------------
__global__ void k_scatter(const int* __restrict__ ei, int e) {
    int i = blockIdx.x * blockDim.x + threadIdx.x;
    if (i < e) {
        int dst = ei[e + i];
        int pos = atomicAdd(&g_cur[dst], 1);
        g_csr[pos] = ei[i];
    }
}

// ------------------------------------------------------------------
// K5: aggregation, 4-edge software pipelining for MLP.
// One warp per dst node; lane owns 4 channels (head = lane>>2).
// ------------------------------------------------------------------
__global__ void k_agg(const float* __restrict__ bias, float* __restrict__ out, int n) {
    int warp = (blockIdx.x * blockDim.x + threadIdx.x) >> 5;
    int lane = threadIdx.x & 31;
    if (warp >= n) return;

    const int h = lane >> 2;
    const float rv = g_right[warp * HH + h];
    const int s0 = g_off[warp], s1 = g_off[warp + 1];
    const unsigned em_off = lane * 4;

    float4 acc = make_float4(0.f, 0.f, 0.f, 0.f);
    float sumw = 0.f;

    for (int base = s0; base < s1; base += 32) {
        int idx = base + lane;
        int sv  = (idx < s1) ? g_csr[idx] : 0;
        int cnt = min(32, s1 - base);

        int j = 0;
        for (; j + 4 <= cnt; j += 4) {
            int sA = __shfl_sync(0xffffffffu, sv, j);
            int sB = __shfl_sync(0xffffffffu, sv, j + 1);
            int sC = __shfl_sync(0xffffffffu, sv, j + 2);
            int sD = __shfl_sync(0xffffffffu, sv, j + 3);

            // batch all loads -> 8 outstanding per warp
            float lA = g_left[sA * HH + h];
            float lB = g_left[sB * HH + h];
            float lC = g_left[sC * HH + h];
            float lD = g_left[sD * HH + h];
            uint2 rA = *(const uint2*)&g_embh[sA * CC + em_off];
            uint2 rB = *(const uint2*)&g_embh[sB * CC + em_off];
            uint2 rC = *(const uint2*)&g_embh[sC * CC + em_off];
            uint2 rD = *(const uint2*)&g_embh[sD * CC + em_off];

            float eA = lA + rv; eA = (eA >= 0.f) ? eA : 0.2f * eA;
            float eB = lB + rv; eB = (eB >= 0.f) ? eB : 0.2f * eB;
            float eC = lC + rv; eC = (eC >= 0.f) ? eC : 0.2f * eC;
            float eD = lD + rv; eD = (eD >= 0.f) ? eD : 0.2f * eD;
            float wA = __expf(eA), wB = __expf(eB);
            float wC = __expf(eC), wD = __expf(eD);
            sumw += (wA + wB) + (wC + wD);

            {
                float2 f0 = __half22float2(*(__half2*)&rA.x);
                float2 f1 = __half22float2(*(__half2*)&rA.y);
                acc.x += wA * f0.x; acc.y += wA * f0.y;
                acc.z += wA * f1.x; acc.w += wA * f1.y;
            }
            {
                float2 f0 = __half22float2(*(__half2*)&rB.x);
                float2 f1 = __half22float2(*(__half2*)&rB.y);
                acc.x += wB * f0.x; acc.y += wB * f0.y;
                acc.z += wB * f1.x; acc.w += wB * f1.y;
            }
            {
                float2 f0 = __half22float2(*(__half2*)&rC.x);
                float2 f1 = __half22float2(*(__half2*)&rC.y);
                acc.x += wC * f0.x; acc.y += wC * f0.y;
                acc.z += wC * f1.x; acc.w += wC * f1.y;
            }
            {
                float2 f0 = __half22float2(*(__half2*)&rD.x);
                float2 f1 = __half22float2(*(__half2*)&rD.y);
                acc.x += wD * f0.x; acc.y += wD * f0.y;
                acc.z += wD * f1.x; acc.w += wD * f1.y;
            }
        }
        for (; j < cnt; j++) {
            int s = __shfl_sync(0xffffffffu, sv, j);
            float l = g_left[s * HH + h];
            uint2 raw = *(const uint2*)&g_embh[s * CC + em_off];
            float e = l + rv;
            e = (e >= 0.f) ? e : 0.2f * e;
            float w = __expf(e);
            float2 f0 = __half22float2(*(__half2*)&raw.x);
            float2 f1 = __half22float2(*(__half2*)&raw.y);
            sumw  += w;
            acc.x += w * f0.x; acc.y += w * f0.y;
            acc.z += w * f1.x; acc.w += w * f1.y;
        }
    }

    float inv = (sumw > 0.f) ? (1.f / sumw) : 0.f;
    int c = lane * 4;
    float4 o;
    o.x = acc.x * inv + bias[c + 0];
    o.y = acc.y * inv + bias[c + 1];
    o.z = acc.z * inv + bias[c + 2];
    o.w = acc.w * inv + bias[c + 3];
    *(float4*)&out[warp * CC + c] = o;
}

// ------------------------------------------------------------------
extern "C" void kernel_launch(void* const* d_in, const int* in_sizes, int n_in,
                              void* d_out, int out_size) {
    const float* X    = (const float*)d_in[0];
    const int*   EI   = (const int*)d_in[1];
    const float* W    = (const float*)d_in[2];
    const float* aL   = (const float*)d_in[3];
    const float* aR   = (const float*)d_in[4];
    const float* bias = (const float*)d_in[5];
    float*       out  = (float*)d_out;

    const int n = in_sizes[0] / CC;   // 50000
    const int e = in_sizes[1] / 2;    // 1600000

    k_zero   <<<(n + 255) / 256, 256>>>(n);
    k_gemm   <<<(n + 63) / 64, 256>>>(X, W, aL, aR, n);
    k_hist   <<<(e + 255) / 256, 256>>>(EI, e);
    k_scanA  <<<NBLK, SCAN_B>>>(n);
    k_scanB  <<<1, SCAN_B>>>(n);
    k_scanC  <<<NBLK, SCAN_B>>>(n);
    k_scatter<<<(e + 255) / 256, 256>>>(EI, e);
    k_agg    <<<(n * 32 + 255) / 256, 256>>>(bias, out, n);
}

// round 8
// speedup vs baseline: 1.6772x; 1.2160x over previous
#include <cuda_runtime.h>
#include <cuda_fp16.h>
#include <cstdint>

#define Nn 50000
#define Ee 1600000
#define CC 128
#define HH 8
#define SCAN_B 1024
#define NBLK ((Nn + SCAN_B - 1) / SCAN_B)   // 49

// ---- scratch (static __device__: allocation-free) ----
__device__ __half g_embh[Nn * CC];   // 12.8 MB (fp16 message values)
__device__ float g_left[Nn * HH];
__device__ float g_right[Nn * HH];
__device__ int   g_deg[Nn];
__device__ int   g_off[Nn + 1];
__device__ int   g_cur[Nn];
__device__ int   g_csr[Ee];          // 6.4 MB
__device__ int   g_bsum[NBLK];
__device__ int   g_bsumx[NBLK];

// ------------------------------------------------------------------
// K0: zero the degree histogram
// ------------------------------------------------------------------
__global__ void k_zero(int n) {
    int i = blockIdx.x * blockDim.x + threadIdx.x;
    if (i < n) g_deg[i] = 0;
}

// ------------------------------------------------------------------
// K1: emb = X @ W^T via mma.sync m16n8k16 (f16 in, f32 acc)
//     + fused left/right logits.
// Block: 256 threads (8 warps), tile 128 nodes x 128 outs, K chunked by 64.
// Warp w computes rows [w*16, w*16+16) x all 128 outs (16 n-tiles of 8).
// ------------------------------------------------------------------
__global__ void k_gemm(const float* __restrict__ X, const float* __restrict__ W,
                       const float* __restrict__ aL, const float* __restrict__ aR, int n) {
    __shared__ __half Xsh[128][72];   // stride 72 halves = 36 words (36%32=4 -> conflict-free)
    __shared__ __half Wsh[128][72];
    __shared__ float  aLs[16][8];
    __shared__ float  aRs[16][8];

    const int tid  = threadIdx.x;
    const int lane = tid & 31;
    const int wid  = tid >> 5;
    const int q    = lane & 3;        // thread-in-group
    const int g    = lane >> 2;       // group id (row within 8)
    const int m0   = blockIdx.x * 128;

    if (tid < 128) {
        aLs[tid >> 3][tid & 7] = aL[tid];
        aRs[tid >> 3][tid & 7] = aR[tid];
    }

    float acc[16][4];
    #pragma unroll
    for (int nt = 0; nt < 16; nt++) {
        acc[nt][0] = 0.f; acc[nt][1] = 0.f; acc[nt][2] = 0.f; acc[nt][3] = 0.f;
    }

    for (int kc = 0; kc < CC; kc += 64) {
        // load X chunk: 128 rows x 64 cols fp32 -> fp16. 2048 float4 / 256 thr = 8 each.
        #pragma unroll
        for (int it = 0; it < 8; it++) {
            int idx = tid + it * 256;
            int r   = idx >> 4;
            int c4  = (idx & 15) * 4;
            int node = m0 + r;
            float4 v = (node < n) ? *(const float4*)&X[node * CC + kc + c4]
                                  : make_float4(0.f, 0.f, 0.f, 0.f);
            *(__half2*)&Xsh[r][c4]     = __floats2half2_rn(v.x, v.y);
            *(__half2*)&Xsh[r][c4 + 2] = __floats2half2_rn(v.z, v.w);
        }
        // load W chunk: 128 outs x 64 cols
        #pragma unroll
        for (int it = 0; it < 8; it++) {
            int idx = tid + it * 256;
            int r   = idx >> 4;
            int c4  = (idx & 15) * 4;
            float4 v = *(const float4*)&W[r * CC + kc + c4];
            *(__half2*)&Wsh[r][c4]     = __floats2half2_rn(v.x, v.y);
            *(__half2*)&Wsh[r][c4 + 2] = __floats2half2_rn(v.z, v.w);
        }
        __syncthreads();

        #pragma unroll
        for (int ks = 0; ks < 4; ks++) {
            const int kb   = ks * 16;
            const int arow = wid * 16 + g;
            const int kcol = kb + q * 2;
            uint32_t a0 = *(const uint32_t*)&Xsh[arow][kcol];
            uint32_t a1 = *(const uint32_t*)&Xsh[arow + 8][kcol];
            uint32_t a2 = *(const uint32_t*)&Xsh[arow][kcol + 8];
            uint32_t a3 = *(const uint32_t*)&Xsh[arow + 8][kcol + 8];
            #pragma unroll
            for (int nt = 0; nt < 16; nt++) {
                const int brow = nt * 8 + g;
                uint32_t b0 = *(const uint32_t*)&Wsh[brow][kcol];
                uint32_t b1 = *(const uint32_t*)&Wsh[brow][kcol + 8];
                asm volatile(
                    "mma.sync.aligned.m16n8k16.row.col.f32.f16.f16.f32 "
                    "{%0,%1,%2,%3}, {%4,%5,%6,%7}, {%8,%9}, {%0,%1,%2,%3};\n"
                    : "+f"(acc[nt][0]), "+f"(acc[nt][1]), "+f"(acc[nt][2]), "+f"(acc[nt][3])
                    : "r"(a0), "r"(a1), "r"(a2), "r"(a3), "r"(b0), "r"(b1));
            }
        }
        __syncthreads();
    }

    // ---- epilogue: emb (fp16) + left/right logits ----
    const int r0    = wid * 16 + g;       // local row (c0,c1)
    const int node0 = m0 + r0;
    const int node1 = node0 + 8;          // local row (c2,c3)

    // store emb
    #pragma unroll
    for (int nt = 0; nt < 16; nt++) {
        int c = nt * 8 + q * 2;
        if (node0 < n) *(__half2*)&g_embh[node0 * CC + c] = __floats2half2_rn(acc[nt][0], acc[nt][1]);
        if (node1 < n) *(__half2*)&g_embh[node1 * CC + c] = __floats2half2_rn(acc[nt][2], acc[nt][3]);
    }

    // logits: head h spans cols 16h..16h+15 = n-tiles {2h, 2h+1}
    float l0v[HH], r0v[HH], l1v[HH], r1v[HH];
    #pragma unroll
    for (int h = 0; h < HH; h++) {
        const int ntA = 2 * h, ntB = 2 * h + 1;
        const int cA = q * 2;        // c_local of acc[ntA][0]
        const int cB = 8 + q * 2;    // c_local of acc[ntB][0]
        float lA = aLs[cA][h],     lA1 = aLs[cA + 1][h];
        float lB = aLs[cB][h],     lB1 = aLs[cB + 1][h];
        float rA = aRs[cA][h],     rA1 = aRs[cA + 1][h];
        float rB = aRs[cB][h],     rB1 = aRs[cB + 1][h];

        float l0 = acc[ntA][0] * lA + acc[ntA][1] * lA1 + acc[ntB][0] * lB + acc[ntB][1] * lB1;
        float r0s = acc[ntA][0] * rA + acc[ntA][1] * rA1 + acc[ntB][0] * rB + acc[ntB][1] * rB1;
        float l1 = acc[ntA][2] * lA + acc[ntA][3] * lA1 + acc[ntB][2] * lB + acc[ntB][3] * lB1;
        float r1s = acc[ntA][2] * rA + acc[ntA][3] * rA1 + acc[ntB][2] * rB + acc[ntB][3] * rB1;

        l0  += __shfl_xor_sync(0xffffffffu, l0, 1);
        l0  += __shfl_xor_sync(0xffffffffu, l0, 2);
        r0s += __shfl_xor_sync(0xffffffffu, r0s, 1);
        r0s += __shfl_xor_sync(0xffffffffu, r0s, 2);
        l1  += __shfl_xor_sync(0xffffffffu, l1, 1);
        l1  += __shfl_xor_sync(0xffffffffu, l1, 2);
        r1s += __shfl_xor_sync(0xffffffffu, r1s, 1);
        r1s += __shfl_xor_sync(0xffffffffu, r1s, 2);

        l0v[h] = l0; r0v[h] = r0s; l1v[h] = l1; r1v[h] = r1s;
    }
    // quad lane q stores heads {2q, 2q+1}
    if (node0 < n) {
        *(float2*)&g_left [node0 * HH + 2 * q] = make_float2(l0v[2 * q], l0v[2 * q + 1]);
        *(float2*)&g_right[node0 * HH + 2 * q] = make_float2(r0v[2 * q], r0v[2 * q + 1]);
    }
    if (node1 < n) {
        *(float2*)&g_left [node1 * HH + 2 * q] = make_float2(l1v[2 * q], l1v[2 * q + 1]);
        *(float2*)&g_right[node1 * HH + 2 * q] = make_float2(r1v[2 * q], r1v[2 * q + 1]);
    }
}

// ------------------------------------------------------------------
// K2: degree histogram over dst
// ------------------------------------------------------------------
__global__ void k_hist(const int* __restrict__ ei, int e) {
    int i = blockIdx.x * blockDim.x + threadIdx.x;
    if (i < e) atomicAdd(&g_deg[ei[e + i]], 1);
}

// ------------------------------------------------------------------
// K3: hierarchical exclusive scan
// ------------------------------------------------------------------
__device__ __forceinline__ int block_scan_incl(int v, int tid, int* wsums) {
    int x = v;
    #pragma unroll
    for (int d = 1; d < 32; d <<= 1) {
        int y = __shfl_up_sync(0xffffffffu, x, d);
        if ((tid & 31) >= d) x += y;
    }
    if ((tid & 31) == 31) wsums[tid >> 5] = x;
    __syncthreads();
    if (tid < 32) {
        int s = wsums[tid];
        #pragma unroll
        for (int d = 1; d < 32; d <<= 1) {
            int y = __shfl_up_sync(0xffffffffu, s, d);
            if (tid >= d) s += y;
        }
        wsums[tid] = s;
    }
    __syncthreads();
    int wp = (tid >= 32) ? wsums[(tid >> 5) - 1] : 0;
    return x + wp;
}

__global__ void k_scanA(int n) {
    __shared__ int wsums[32];
    int tid = threadIdx.x;
    int i = blockIdx.x * SCAN_B + tid;
    int v = (i < n) ? g_deg[i] : 0;
    int incl = block_scan_incl(v, tid, wsums);
    if (i < n) g_off[i] = incl - v;
    if (tid == SCAN_B - 1) g_bsum[blockIdx.x] = incl;
}

__global__ void k_scanB(int n) {
    __shared__ int wsums[32];
    int tid = threadIdx.x;
    int v = (tid < NBLK) ? g_bsum[tid] : 0;
    int incl = block_scan_incl(v, tid, wsums);
    if (tid < NBLK) g_bsumx[tid] = incl - v;
    if (tid == NBLK - 1) g_off[n] = incl;
}

__global__ void k_scanC(int n) {
    int i = blockIdx.x * SCAN_B + threadIdx.x;
    if (i < n) {
        int o = g_off[i] + g_bsumx[blockIdx.x];
        g_off[i] = o;
        g_cur[i] = o;
    }
}

// ------------------------------------------------------------------
// K4: scatter edges into CSR (by dst), storing src
// ------------------------------------------------------------------
__global__ void k_scatter(const int* __restrict__ ei, int e) {
    int i = blockIdx.x * blockDim.x + threadIdx.x;
    if (i < e) {
        int dst = ei[e + i];
        int pos = atomicAdd(&g_cur[dst], 1);
        g_csr[pos] = ei[i];
    }
}

// ------------------------------------------------------------------
// K5: aggregation, 8-edge software pipelining for MLP.
// One warp per dst node; lane owns 4 channels (head = lane>>2).
// ------------------------------------------------------------------
__global__ void k_agg(const float* __restrict__ bias, float* __restrict__ out, int n) {
    int warp = (blockIdx.x * blockDim.x + threadIdx.x) >> 5;
    int lane = threadIdx.x & 31;
    if (warp >= n) return;

    const int h = lane >> 2;
    const float rv = g_right[warp * HH + h];
    const int s0 = g_off[warp], s1 = g_off[warp + 1];
    const unsigned em_off = lane * 4;

    float4 acc = make_float4(0.f, 0.f, 0.f, 0.f);
    float sumw = 0.f;

    for (int base = s0; base < s1; base += 32) {
        int idx = base + lane;
        int sv  = (idx < s1) ? g_csr[idx] : 0;
        int cnt = min(32, s1 - base);

        int j = 0;
        for (; j + 8 <= cnt; j += 8) {
            int   s[8]; float lv[8]; uint2 r[8];
            #pragma unroll
            for (int u = 0; u < 8; u++) s[u] = __shfl_sync(0xffffffffu, sv, j + u);
            #pragma unroll
            for (int u = 0; u < 8; u++) lv[u] = g_left[s[u] * HH + h];
            #pragma unroll
            for (int u = 0; u < 8; u++) r[u] = *(const uint2*)&g_embh[s[u] * CC + em_off];
            #pragma unroll
            for (int u = 0; u < 8; u++) {
                float e = lv[u] + rv;
                e = (e >= 0.f) ? e : 0.2f * e;
                float w = __expf(e);
                float2 f0 = __half22float2(*(__half2*)&r[u].x);
                float2 f1 = __half22float2(*(__half2*)&r[u].y);
                sumw  += w;
                acc.x += w * f0.x; acc.y += w * f0.y;
                acc.z += w * f1.x; acc.w += w * f1.y;
            }
        }
        for (; j < cnt; j++) {
            int s = __shfl_sync(0xffffffffu, sv, j);
            float l = g_left[s * HH + h];
            uint2 raw = *(const uint2*)&g_embh[s * CC + em_off];
            float e = l + rv;
            e = (e >= 0.f) ? e : 0.2f * e;
            float w = __expf(e);
            float2 f0 = __half22float2(*(__half2*)&raw.x);
            float2 f1 = __half22float2(*(__half2*)&raw.y);
            sumw  += w;
            acc.x += w * f0.x; acc.y += w * f0.y;
            acc.z += w * f1.x; acc.w += w * f1.y;
        }
    }

    float inv = (sumw > 0.f) ? (1.f / sumw) : 0.f;
    int c = lane * 4;
    float4 o;
    o.x = acc.x * inv + bias[c + 0];
    o.y = acc.y * inv + bias[c + 1];
    o.z = acc.z * inv + bias[c + 2];
    o.w = acc.w * inv + bias[c + 3];
    *(float4*)&out[warp * CC + c] = o;
}

// ------------------------------------------------------------------
extern "C" void kernel_launch(void* const* d_in, const int* in_sizes, int n_in,
                              void* d_out, int out_size) {
    const float* X    = (const float*)d_in[0];
    const int*   EI   = (const int*)d_in[1];
    const float* W    = (const float*)d_in[2];
    const float* aL   = (const float*)d_in[3];
    const float* aR   = (const float*)d_in[4];
    const float* bias = (const float*)d_in[5];
    float*       out  = (float*)d_out;

    const int n = in_sizes[0] / CC;   // 50000
    const int e = in_sizes[1] / 2;    // 1600000

    k_zero   <<<(n + 255) / 256, 256>>>(n);
    k_gemm   <<<(n + 127) / 128, 256>>>(X, W, aL, aR, n);
    k_hist   <<<(e + 255) / 256, 256>>>(EI, e);
    k_scanA  <<<NBLK, SCAN_B>>>(n);
    k_scanB  <<<1, SCAN_B>>>(n);
    k_scanC  <<<NBLK, SCAN_B>>>(n);
    k_scatter<<<(e + 255) / 256, 256>>>(EI, e);
    k_agg    <<<(n * 32 + 255) / 256, 256>>>(bias, out, n);
}